// round 5
// baseline (speedup 1.0000x reference)
#include <cuda_runtime.h>
#include <cuda_bf16.h>
#include <math.h>
#include <stdint.h>

#define BB   2048
#define INN  512
#define HH   512
#define KFR  32
#define OUTN 512
#define KD   1536            // IN + 2H (combined_d width)
#define KC   1024            // IN + H
#define BH   (BB*HH)

#define OFF_WI   0
#define OFF_WO   (512*1024)
#define OFF_WC   (2*512*1024)
#define OFF_WF   (3*512*1024)
#define OFF_WOUT (3*512*1024 + 512*1536)
#define W_TOTAL  (OFF_WOUT + 512*512)

// 128x256 CTA tile, K-chunk 64.
// Stage layout: A_hi 16KB | A_lo 16KB | B_hi 32KB | B_lo 32KB = 96KB
#define A_TILE_B 16384
#define B_TILE_B 32768
#define STAGE_B  98304
#define SMEM_TOT (2*STAGE_B)   // 196608

// ---------------- static device scratch ----------------
__device__ __nv_bfloat16 g_comb_hi[BB*KD];
__device__ __nv_bfloat16 g_comb_lo[BB*KD];
__device__ __nv_bfloat16 g_w_hi[W_TOTAL];
__device__ __nv_bfloat16 g_w_lo[W_TOTAL];
__device__ __nv_bfloat16 g_hid_hi[BH];
__device__ __nv_bfloat16 g_hid_lo[BH];
__device__ float g_z[4][BH];          // pre-activations: 0=i, 1=o, 2=c, 3=f

// ---------------- PTX helpers (baseline ISA only) ----------------
__device__ __forceinline__ uint32_t smem_u32(const void* p) {
    return (uint32_t)__cvta_generic_to_shared(p);
}

__device__ __forceinline__ void cp16(uint32_t daddr, const void* g) {
    asm volatile("cp.async.cg.shared.global [%0], [%1], 16;" :: "r"(daddr), "l"(g) : "memory");
}
#define CP_COMMIT() asm volatile("cp.async.commit_group;" ::: "memory")
template <int N>
__device__ __forceinline__ void cp_wait() {
    asm volatile("cp.async.wait_group %0;" :: "n"(N) : "memory");
}

__device__ __forceinline__ void ldsm4(uint32_t addr, uint32_t* r) {
    asm volatile("ldmatrix.sync.aligned.m8n8.x4.shared.b16 {%0,%1,%2,%3}, [%4];"
        : "=r"(r[0]), "=r"(r[1]), "=r"(r[2]), "=r"(r[3]) : "r"(addr));
}

__device__ __forceinline__ void mma_bf16(float* c, const uint32_t* a, const uint32_t* b) {
    asm volatile("mma.sync.aligned.m16n8k16.row.col.f32.bf16.bf16.f32 "
        "{%0,%1,%2,%3}, {%4,%5,%6,%7}, {%8,%9}, {%0,%1,%2,%3};"
        : "+f"(c[0]), "+f"(c[1]), "+f"(c[2]), "+f"(c[3])
        : "r"(a[0]), "r"(a[1]), "r"(a[2]), "r"(a[3]), "r"(b[0]), "r"(b[1]));
}

// ---------------------------------------------------------------------------
// cp.async loader: one K-chunk (64 cols) of A(128 rows) + B(256 rows), hi+lo.
// 256 threads. swizzle: phys_col16 = col16 ^ (row & 7)
// ---------------------------------------------------------------------------
__device__ __forceinline__ void load_stage(uint32_t sbase,
    const char* aH, const char* aL, const char* bH, const char* bL,
    int lda_b, int ldb_b, int k0b, int tid) {
#pragma unroll
    for (int i = 0; i < 4; i++) {           // A: 128 rows x 8 chunks = 1024 cp16/tile
        int idx = i * 256 + tid;
        int row = idx >> 3;
        uint32_t ch  = (uint32_t)(idx & 7) * 16;
        uint32_t off = (uint32_t)row * 128 + (ch ^ (((uint32_t)row & 7) << 4));
        const size_t go = (size_t)row * lda_b + k0b + ch;
        cp16(sbase + off, aH + go);
        cp16(sbase + A_TILE_B + off, aL + go);
    }
#pragma unroll
    for (int i = 0; i < 8; i++) {           // B: 256 rows x 8 chunks = 2048 cp16/tile
        int idx = i * 256 + tid;
        int row = idx >> 3;
        uint32_t ch  = (uint32_t)(idx & 7) * 16;
        uint32_t off = (uint32_t)row * 128 + (ch ^ (((uint32_t)row & 7) << 4));
        const size_t go = (size_t)row * ldb_b + k0b + ch;
        cp16(sbase + 2 * A_TILE_B + off, bH + go);
        cp16(sbase + 2 * A_TILE_B + B_TILE_B + off, bL + go);
    }
}

// ---------------------------------------------------------------------------
// split-bf16 mma.sync GEMM tile: C[m,n] = sum_k A[m,k]*B[n,k] + bias[n]
// 128x256 tile, 8 warps (2M x 4N), warp tile 64x64, 2-stage cp.async pipeline.
// ---------------------------------------------------------------------------
__device__ __forceinline__ void mma_gemm_tile(
    const __nv_bfloat16* Ahi, const __nv_bfloat16* Alo, int lda,
    const __nv_bfloat16* Bhi, const __nv_bfloat16* Blo, int ldb,
    const float* __restrict__ bias, float* __restrict__ C, int ldc,
    int K, int blockM, int blockN) {
    extern __shared__ __align__(1024) char dsm[];
    const int tid  = threadIdx.x;
    const int lane = tid & 31;
    const int wid  = tid >> 5;
    const int wm   = wid & 1;    // 0..1 -> 64-row slab
    const int wn   = wid >> 1;   // 0..3 -> 64-col slab
    uint32_t sb = smem_u32(dsm);

    const uint32_t a_kb = ((uint32_t)lane >> 4) * 16;          // 0/16
    const uint32_t b_kb = (((uint32_t)lane >> 3) & 1) * 16;    // 0/16
    uint32_t aRow[4], aXor[4];
#pragma unroll
    for (int mt = 0; mt < 4; mt++) {
        int r = wm * 64 + mt * 16 + (lane & 15);
        aRow[mt] = (uint32_t)r * 128;
        aXor[mt] = ((uint32_t)r & 7) << 4;
    }
    uint32_t bRow[4], bXor[4];
#pragma unroll
    for (int g = 0; g < 4; g++) {
        int r = wn * 64 + g * 16 + (((lane >> 4) << 3) + (lane & 7));
        bRow[g] = (uint32_t)r * 128;
        bXor[g] = ((uint32_t)r & 7) << 4;
    }

    float acc[4][8][4];
#pragma unroll
    for (int mt = 0; mt < 4; mt++)
#pragma unroll
        for (int nt = 0; nt < 8; nt++)
#pragma unroll
            for (int j = 0; j < 4; j++) acc[mt][nt][j] = 0.0f;

    const char* aH = (const char*)(Ahi + (size_t)blockM * lda);
    const char* aL = (const char*)(Alo + (size_t)blockM * lda);
    const char* bH = (const char*)(Bhi + (size_t)blockN * ldb);
    const char* bL = (const char*)(Blo + (size_t)blockN * ldb);
    const int lda_b = lda * 2, ldb_b = ldb * 2;
    const int NC = K / 64;

    // prologue: both stages in flight
    load_stage(sb, aH, aL, bH, bL, lda_b, ldb_b, 0, tid);
    CP_COMMIT();
    load_stage(sb + STAGE_B, aH, aL, bH, bL, lda_b, ldb_b, 128, tid);
    CP_COMMIT();

    for (int c = 0; c < NC; ++c) {
        cp_wait<1>();          // chunk c resident
        __syncthreads();

        const uint32_t st = sb + (uint32_t)(c & 1) * STAGE_B;
#pragma unroll
        for (int kk = 0; kk < 4; kk++) {
            uint32_t ah[4][4], al[4][4];
#pragma unroll
            for (int mt = 0; mt < 4; mt++) {
                uint32_t col = ((uint32_t)(kk * 32) + a_kb) ^ aXor[mt];
                ldsm4(st + aRow[mt] + col, ah[mt]);
                ldsm4(st + A_TILE_B + aRow[mt] + col, al[mt]);
            }
#pragma unroll
            for (int g = 0; g < 4; g++) {
                uint32_t col = ((uint32_t)(kk * 32) + b_kb) ^ bXor[g];
                uint32_t bh[4], bl[4];
                ldsm4(st + 2 * A_TILE_B + bRow[g] + col, bh);
                ldsm4(st + 2 * A_TILE_B + B_TILE_B + bRow[g] + col, bl);
#pragma unroll
                for (int mt = 0; mt < 4; mt++) {
                    mma_bf16(acc[mt][2*g],   ah[mt], bh);
                    mma_bf16(acc[mt][2*g],   ah[mt], bl);
                    mma_bf16(acc[mt][2*g],   al[mt], bh);
                    mma_bf16(acc[mt][2*g+1], ah[mt], bh + 2);
                    mma_bf16(acc[mt][2*g+1], ah[mt], bl + 2);
                    mma_bf16(acc[mt][2*g+1], al[mt], bh + 2);
                }
            }
        }
        __syncthreads();       // all warps done reading stage c&1
        if (c + 2 < NC) {
            load_stage(sb + (uint32_t)(c & 1) * STAGE_B, aH, aL, bH, bL,
                       lda_b, ldb_b, (c + 2) * 128, tid);
        }
        CP_COMMIT();           // uniform group accounting (may be empty)
    }

    // epilogue: add bias, store fp32
#pragma unroll
    for (int mt = 0; mt < 4; mt++) {
        int r0 = blockM + wm * 64 + mt * 16 + (lane >> 2);
#pragma unroll
        for (int nt = 0; nt < 8; nt++) {
            int col = blockN + wn * 64 + nt * 8 + (lane & 3) * 2;
            float b0 = bias[col], b1 = bias[col + 1];
            float2 v0 = {acc[mt][nt][0] + b0, acc[mt][nt][1] + b1};
            float2 v1 = {acc[mt][nt][2] + b0, acc[mt][nt][3] + b1};
            *(float2*)(C + (size_t)r0 * ldc + col) = v0;
            *(float2*)(C + (size_t)(r0 + 8) * ldc + col) = v1;
        }
    }
}

// ---------------------------------------------------------------------------
// z order: 0 = Wf (K=1536, longest), then i, o, c.  Grid (2, 16, 4).
__global__ __launch_bounds__(256, 1)
void gates_mma_kernel(const float* __restrict__ bi, const float* __restrict__ bo,
                      const float* __restrict__ bc, const float* __restrict__ bf) {
    int z = blockIdx.z;
    const __nv_bfloat16 *wh, *wl; const float* bias; int K; float* dst;
    if      (z == 0) { wh = g_w_hi + OFF_WF; wl = g_w_lo + OFF_WF; bias = bf; K = KD; dst = g_z[3]; }
    else if (z == 1) { wh = g_w_hi + OFF_WI; wl = g_w_lo + OFF_WI; bias = bi; K = KC; dst = g_z[0]; }
    else if (z == 2) { wh = g_w_hi + OFF_WO; wl = g_w_lo + OFF_WO; bias = bo; K = KC; dst = g_z[1]; }
    else             { wh = g_w_hi + OFF_WC; wl = g_w_lo + OFF_WC; bias = bc; K = KC; dst = g_z[2]; }
    mma_gemm_tile(g_comb_hi, g_comb_lo, KD, wh, wl, K, bias, dst, HH, K,
                  blockIdx.y * 128, blockIdx.x * 256);
}

__global__ __launch_bounds__(256, 1)
void out_mma_kernel(const float* __restrict__ bout, float* __restrict__ out) {
    mma_gemm_tile(g_hid_hi, g_hid_lo, HH,
                  g_w_hi + OFF_WOUT, g_w_lo + OFF_WOUT, HH,
                  bout, out, OUTN, HH, blockIdx.y * 128, blockIdx.x * 256);
}

// ---------------------------------------------------------------------------
// conversions: fp32 -> bf16 hi/lo split
// ---------------------------------------------------------------------------
__device__ __forceinline__ void split4(float4 v, __nv_bfloat16* hi, __nv_bfloat16* lo) {
    float f[4] = {v.x, v.y, v.z, v.w};
    union { __nv_bfloat16 h[4]; uint2 u; } H, L;
#pragma unroll
    for (int i = 0; i < 4; i++) {
        __nv_bfloat16 h = __float2bfloat16_rn(f[i]);
        H.h[i] = h;
        L.h[i] = __float2bfloat16_rn(f[i] - __bfloat162float(h));
    }
    *(uint2*)hi = H.u;
    *(uint2*)lo = L.u;
}

__global__ void comb_conv_kernel(const float* __restrict__ sample,
                                 const float* __restrict__ hidden,
                                 const float* __restrict__ d0) {
    int idx = blockIdx.x * blockDim.x + threadIdx.x;   // over BB*KD/4
    if (idx >= BB * KD / 4) return;
    int b  = idx / (KD / 4);
    int c4 = idx % (KD / 4);
    float4 v;
    if (c4 < INN / 4)            v = ((const float4*)sample)[b * (INN/4) + c4];
    else if (c4 < (INN+HH) / 4)  v = ((const float4*)hidden)[b * (HH/4) + (c4 - INN/4)];
    else                         v = ((const float4*)d0)[b * (HH/4) + (c4 - (INN+HH)/4)];
    split4(v, g_comb_hi + idx * 4, g_comb_lo + idx * 4);
}

__global__ void w_conv_kernel(const float* __restrict__ Wi, const float* __restrict__ Wo,
                              const float* __restrict__ Wc, const float* __restrict__ Wf,
                              const float* __restrict__ Wout) {
    int a = blockIdx.y;
    const float* src; size_t off; int n;
    if      (a == 0) { src = Wi;   off = OFF_WI;   n = 512 * 1024; }
    else if (a == 1) { src = Wo;   off = OFF_WO;   n = 512 * 1024; }
    else if (a == 2) { src = Wc;   off = OFF_WC;   n = 512 * 1024; }
    else if (a == 3) { src = Wf;   off = OFF_WF;   n = 512 * 1536; }
    else             { src = Wout; off = OFF_WOUT; n = 512 * 512;  }
    int i = blockIdx.x * blockDim.x + threadIdx.x;
    if (i * 4 >= n) return;
    float4 v = ((const float4*)src)[i];
    split4(v, g_w_hi + off + (size_t)i * 4, g_w_lo + off + (size_t)i * 4);
}

// ---------------------------------------------------------------------------
// fused elementwise + bf16 split of hidden_new; next-slice prefetch for MLP
// ---------------------------------------------------------------------------
__device__ __forceinline__ float sigf(float x) { return 1.0f / (1.0f + expf(-x)); }

__global__ void fused_cell_kernel(const float* __restrict__ cell_t,
                                  float* __restrict__ dout) {
    int idx = blockIdx.x * blockDim.x + threadIdx.x;   // over BH/4
    const int nb4 = BH / 4;
    if (idx >= nb4) return;

    const float4* c4  = (const float4*)cell_t;
    float4* hid = (float4*)(dout + (size_t)BB * OUTN);
    float4* hc  = (float4*)(dout + (size_t)2 * BB * OUTN);
    float4* dv  = (float4*)(dout + (size_t)2 * BB * OUTN + (size_t)KFR * BH);

    float4 zf = ((const float4*)g_z[3])[idx];
    float4 d;
    d.x = 0.5f * sigf(zf.x); d.y = 0.5f * sigf(zf.y);
    d.z = 0.5f * sigf(zf.z); d.w = 0.5f * sigf(zf.w);
    dv[idx] = d;

    float4 w   = make_float4(1.f, 1.f, 1.f, 1.f);
    float4 acc = make_float4(0.f, 0.f, 0.f, 0.f);
    float4 cv  = c4[(size_t)(KFR - 1) * nb4 + idx];
#pragma unroll
    for (int j = KFR - 1; j >= 0; j--) {
        float4 nxt;
        if (j >= 1) nxt = c4[(size_t)(j - 1) * nb4 + idx];   // prefetch next slice
        float fi  = (float)(KFR - 1 - j);
        float inv = 1.0f / (float)(KFR - j);
        w.x *= (fi - d.x) * inv;  w.y *= (fi - d.y) * inv;
        w.z *= (fi - d.z) * inv;  w.w *= (fi - d.w) * inv;
        acc.x = fmaf(w.x, cv.x, acc.x);  acc.y = fmaf(w.y, cv.y, acc.y);
        acc.z = fmaf(w.z, cv.z, acc.z);  acc.w = fmaf(w.w, cv.w, acc.w);
        if (j >= 1) { hc[(size_t)(j - 1) * nb4 + idx] = cv; cv = nxt; }
    }

    float4 zi = ((const float4*)g_z[0])[idx];
    float4 zo = ((const float4*)g_z[1])[idx];
    float4 zc = ((const float4*)g_z[2])[idx];

    float4 cell;
    cell.x = -acc.x + tanhf(zc.x) * sigf(zi.x);
    cell.y = -acc.y + tanhf(zc.y) * sigf(zi.y);
    cell.z = -acc.z + tanhf(zc.z) * sigf(zi.z);
    cell.w = -acc.w + tanhf(zc.w) * sigf(zi.w);
    hc[(size_t)(KFR - 1) * nb4 + idx] = cell;

    float4 hn;
    hn.x = tanhf(cell.x) * sigf(zo.x);
    hn.y = tanhf(cell.y) * sigf(zo.y);
    hn.z = tanhf(cell.z) * sigf(zo.z);
    hn.w = tanhf(cell.w) * sigf(zo.w);
    hid[idx] = hn;

    split4(hn, g_hid_hi + idx * 4, g_hid_lo + idx * 4);
}

// ---------------------------------------------------------------------------
extern "C" void kernel_launch(void* const* d_in, const int* in_sizes, int n_in,
                              void* d_out_v, int out_size) {
    const float* sample = (const float*)d_in[0];
    const float* hidden = (const float*)d_in[1];
    const float* cell_t = (const float*)d_in[2];
    const float* d0     = (const float*)d_in[3];
    const float* Wc     = (const float*)d_in[4];
    const float* bc     = (const float*)d_in[5];
    const float* Wi     = (const float*)d_in[6];
    const float* bi     = (const float*)d_in[7];
    const float* Wf     = (const float*)d_in[8];
    const float* bf     = (const float*)d_in[9];
    const float* Wo     = (const float*)d_in[10];
    const float* bo     = (const float*)d_in[11];
    const float* Wout   = (const float*)d_in[12];
    const float* bout   = (const float*)d_in[13];
    float* out = (float*)d_out_v;

    cudaFuncSetAttribute(gates_mma_kernel,
                         cudaFuncAttributeMaxDynamicSharedMemorySize, SMEM_TOT);
    cudaFuncSetAttribute(out_mma_kernel,
                         cudaFuncAttributeMaxDynamicSharedMemorySize, SMEM_TOT);

    // 1) build bf16 hi/lo of combined_d and all weights
    comb_conv_kernel<<<(BB * KD / 4 + 255) / 256, 256>>>(sample, hidden, d0);
    dim3 wgrid((512 * 1536 / 4 + 255) / 256, 5);
    w_conv_kernel<<<wgrid, 256>>>(Wi, Wo, Wc, Wf, Wout);

    // 2) 4 gate GEMMs, 128x256 tiles, single wave (128 CTAs)
    dim3 ggrid(2, 16, 4);
    gates_mma_kernel<<<ggrid, 256, SMEM_TOT>>>(bi, bo, bc, bf);

    // 3) fused elementwise + hidden_new bf16 split
    fused_cell_kernel<<<(BH / 4 + 255) / 256, 256>>>(cell_t, out);

    // 4) output GEMM
    dim3 ogrid(2, 16, 1);
    out_mma_kernel<<<ogrid, 256, SMEM_TOT>>>(bout, out);
}

// round 6
// speedup vs baseline: 1.0845x; 1.0845x over previous
#include <cuda_runtime.h>
#include <cuda_bf16.h>
#include <math.h>
#include <stdint.h>

#define BB   2048
#define INN  512
#define HH   512
#define KFR  32
#define OUTN 512
#define KD   1536            // IN + 2H (combined_d width)
#define KC   1024            // IN + H
#define BH   (BB*HH)

#define OFF_WI   0
#define OFF_WO   (512*1024)
#define OFF_WC   (2*512*1024)
#define OFF_WF   (3*512*1024)
#define OFF_WOUT (3*512*1024 + 512*1536)
#define W_TOTAL  (OFF_WOUT + 512*512)

#define TILE_B   16384       // one 128x64 bf16 tile in smem
#define STAGE_B  (4*TILE_B)  // Ahi, Alo, Bhi, Blo
#define NSTAGE   3
#define SMEM_TOT (NSTAGE*STAGE_B)   // 196608

// copy duty: h_c_1[0..30] = cell_tensor[1..31], 31*BH floats = 8126464 float4
#define COPY_F4_TOTAL  8126464
#define COPY_F4_CTA    31744          // / 256 CTAs
#define COPY_PER_THR   248            // / 128 copy threads

// ---------------- static device scratch ----------------
__device__ __nv_bfloat16 g_comb_hi[BB*KD];
__device__ __nv_bfloat16 g_comb_lo[BB*KD];
__device__ __nv_bfloat16 g_w_hi[W_TOTAL];
__device__ __nv_bfloat16 g_w_lo[W_TOTAL];
__device__ __nv_bfloat16 g_hid_hi[BH];
__device__ __nv_bfloat16 g_hid_lo[BH];
__device__ float g_z[4][BH];          // pre-activations: 0=i, 1=o, 2=c, 3=f

// ---------------- PTX helpers (baseline ISA only) ----------------
__device__ __forceinline__ uint32_t smem_u32(const void* p) {
    return (uint32_t)__cvta_generic_to_shared(p);
}

__device__ __forceinline__ void cp16(uint32_t daddr, const void* g) {
    asm volatile("cp.async.cg.shared.global [%0], [%1], 16;" :: "r"(daddr), "l"(g) : "memory");
}
#define CP_COMMIT() asm volatile("cp.async.commit_group;" ::: "memory")
template <int N>
__device__ __forceinline__ void cp_wait() {
    asm volatile("cp.async.wait_group %0;" :: "n"(N) : "memory");
}

__device__ __forceinline__ void ldsm4(uint32_t addr, uint32_t* r) {
    asm volatile("ldmatrix.sync.aligned.m8n8.x4.shared.b16 {%0,%1,%2,%3}, [%4];"
        : "=r"(r[0]), "=r"(r[1]), "=r"(r[2]), "=r"(r[3]) : "r"(addr));
}

__device__ __forceinline__ void mma_bf16(float* c, const uint32_t* a, const uint32_t* b) {
    asm volatile("mma.sync.aligned.m16n8k16.row.col.f32.bf16.bf16.f32 "
        "{%0,%1,%2,%3}, {%4,%5,%6,%7}, {%8,%9}, {%0,%1,%2,%3};"
        : "+f"(c[0]), "+f"(c[1]), "+f"(c[2]), "+f"(c[3])
        : "r"(a[0]), "r"(a[1]), "r"(a[2]), "r"(a[3]), "r"(b[0]), "r"(b[1]));
}

// ---------------------------------------------------------------------------
// cp.async loader: one K-chunk (64 cols) of the 4 tiles into one stage.
// 256 GEMM threads; per tile 128 rows x 8 x 16B chunks = 1024 cp16 -> 4/thread
// swizzle: phys_col16 = col16 ^ (row & 7)
// ---------------------------------------------------------------------------
__device__ __forceinline__ void load_stage(uint32_t sbase,
    const char* a_hi, const char* a_lo, const char* b_hi, const char* b_lo,
    int lda_b, int ldb_b, int k0b, int tid) {
    const char* srcs[4] = {a_hi, a_lo, b_hi, b_lo};
    const int lds[4] = {lda_b, lda_b, ldb_b, ldb_b};
#pragma unroll
    for (int t = 0; t < 4; t++) {
#pragma unroll
        for (int i = 0; i < 4; i++) {
            int idx = i * 256 + tid;
            int row = idx >> 3;
            uint32_t ch = (uint32_t)(idx & 7) * 16;
            uint32_t off = (uint32_t)row * 128 + (ch ^ (((uint32_t)row & 7) << 4));
            cp16(sbase + t * TILE_B + off,
                 srcs[t] + (size_t)row * lds[t] + k0b + ch);
        }
    }
}

// ---------------------------------------------------------------------------
// split-bf16 mma.sync GEMM tile (8 warps, 128x128 tile, 3-stage pipeline)
// Runs on tid 0..255; copy warps (tid 256..383) execute copy_path instead and
// hit the same __syncthreads count (NC per CTA).
// ---------------------------------------------------------------------------
__device__ __forceinline__ void mma_gemm_tile(
    const __nv_bfloat16* Ahi, const __nv_bfloat16* Alo, int lda,
    const __nv_bfloat16* Bhi, const __nv_bfloat16* Blo, int ldb,
    const float* __restrict__ bias, float* __restrict__ C, int ldc,
    int K, int blockM, int blockN) {
    extern __shared__ __align__(1024) char dsm[];
    const int tid  = threadIdx.x;
    const int lane = tid & 31;
    const int wid  = tid >> 5;
    const int wm   = wid & 3;    // 0..3 -> 32-row slab
    const int wn   = wid >> 2;   // 0..1 -> 64-col slab
    uint32_t sb = smem_u32(dsm);

    const uint32_t a_kb = ((uint32_t)lane >> 4) * 16;          // 0/16
    const uint32_t b_kb = (((uint32_t)lane >> 3) & 1) * 16;    // 0/16
    uint32_t aRow[2], aXor[2];
#pragma unroll
    for (int mt = 0; mt < 2; mt++) {
        int r = wm * 32 + mt * 16 + (lane & 15);
        aRow[mt] = (uint32_t)r * 128;
        aXor[mt] = ((uint32_t)r & 7) << 4;
    }
    uint32_t bRow[4], bXor[4];
#pragma unroll
    for (int g = 0; g < 4; g++) {
        int r = wn * 64 + g * 16 + (((lane >> 4) << 3) + (lane & 7));
        bRow[g] = (uint32_t)r * 128;
        bXor[g] = ((uint32_t)r & 7) << 4;
    }

    float acc[2][8][4];
#pragma unroll
    for (int mt = 0; mt < 2; mt++)
#pragma unroll
        for (int nt = 0; nt < 8; nt++)
#pragma unroll
            for (int j = 0; j < 4; j++) acc[mt][nt][j] = 0.0f;

    const char* aH = (const char*)(Ahi + (size_t)blockM * lda);
    const char* aL = (const char*)(Alo + (size_t)blockM * lda);
    const char* bH = (const char*)(Bhi + (size_t)blockN * ldb);
    const char* bL = (const char*)(Blo + (size_t)blockN * ldb);
    const int lda_b = lda * 2, ldb_b = ldb * 2;
    const int NC = K / 64;

    load_stage(sb, aH, aL, bH, bL, lda_b, ldb_b, 0, tid);
    CP_COMMIT();
    load_stage(sb + STAGE_B, aH, aL, bH, bL, lda_b, ldb_b, 128, tid);
    CP_COMMIT();

    int stage = 0;
    for (int c = 0; c < NC; ++c) {
        cp_wait<1>();
        __syncthreads();
        if (c + 2 < NC) {
            int s2 = stage + 2; if (s2 >= NSTAGE) s2 -= NSTAGE;
            load_stage(sb + (uint32_t)s2 * STAGE_B, aH, aL, bH, bL,
                       lda_b, ldb_b, (c + 2) * 128, tid);
        }
        CP_COMMIT();

        const uint32_t st = sb + (uint32_t)stage * STAGE_B;
#pragma unroll
        for (int kk = 0; kk < 4; kk++) {
            uint32_t ah[2][4], al[2][4];
#pragma unroll
            for (int mt = 0; mt < 2; mt++) {
                uint32_t col = ((uint32_t)(kk * 32) + a_kb) ^ aXor[mt];
                ldsm4(st + 0 * TILE_B + aRow[mt] + col, ah[mt]);
                ldsm4(st + 1 * TILE_B + aRow[mt] + col, al[mt]);
            }
            uint32_t bh[8][2], bl[8][2];
#pragma unroll
            for (int g = 0; g < 4; g++) {
                uint32_t col = ((uint32_t)(kk * 32) + b_kb) ^ bXor[g];
                uint32_t r[4];
                ldsm4(st + 2 * TILE_B + bRow[g] + col, r);
                bh[2*g][0] = r[0]; bh[2*g][1] = r[1];
                bh[2*g+1][0] = r[2]; bh[2*g+1][1] = r[3];
                ldsm4(st + 3 * TILE_B + bRow[g] + col, r);
                bl[2*g][0] = r[0]; bl[2*g][1] = r[1];
                bl[2*g+1][0] = r[2]; bl[2*g+1][1] = r[3];
            }
#pragma unroll
            for (int mt = 0; mt < 2; mt++)
#pragma unroll
                for (int nt = 0; nt < 8; nt++) {
                    mma_bf16(acc[mt][nt], ah[mt], bh[nt]);
                    mma_bf16(acc[mt][nt], ah[mt], bl[nt]);
                    mma_bf16(acc[mt][nt], al[mt], bh[nt]);
                }
        }
        if (++stage >= NSTAGE) stage = 0;
    }

#pragma unroll
    for (int mt = 0; mt < 2; mt++) {
        int r0 = blockM + wm * 32 + mt * 16 + (lane >> 2);
#pragma unroll
        for (int nt = 0; nt < 8; nt++) {
            int col = blockN + wn * 64 + nt * 8 + (lane & 3) * 2;
            float b0 = bias[col], b1 = bias[col + 1];
            float2 v0 = {acc[mt][nt][0] + b0, acc[mt][nt][1] + b1};
            float2 v1 = {acc[mt][nt][2] + b0, acc[mt][nt][3] + b1};
            *(float2*)(C + (size_t)r0 * ldc + col) = v0;
            *(float2*)(C + (size_t)(r0 + 8) * ldc + col) = v1;
        }
    }
}

// ---------------------------------------------------------------------------
// gates GEMM + overlapped h_c_1 shift-copy.
// 384 threads: warps 0-7 GEMM, warps 8-11 copy 31 slices of cell_tensor into
// the h_c_1 region of d_out. Both paths execute exactly NC __syncthreads.
// ---------------------------------------------------------------------------
__global__ __launch_bounds__(384, 1)
void gates_mma_kernel(const float* __restrict__ bi, const float* __restrict__ bo,
                      const float* __restrict__ bc, const float* __restrict__ bf,
                      const float* __restrict__ cell_t, float* __restrict__ dout) {
    int z = blockIdx.z;
    const __nv_bfloat16 *wh, *wl; const float* bias; int K; float* dst;
    if      (z == 0) { wh = g_w_hi + OFF_WF; wl = g_w_lo + OFF_WF; bias = bf; K = KD; dst = g_z[3]; }
    else if (z == 1) { wh = g_w_hi + OFF_WI; wl = g_w_lo + OFF_WI; bias = bi; K = KC; dst = g_z[0]; }
    else if (z == 2) { wh = g_w_hi + OFF_WO; wl = g_w_lo + OFF_WO; bias = bo; K = KC; dst = g_z[1]; }
    else             { wh = g_w_hi + OFF_WC; wl = g_w_lo + OFF_WC; bias = bc; K = KC; dst = g_z[2]; }

    if (threadIdx.x < 256) {
        mma_gemm_tile(g_comb_hi, g_comb_lo, KD, wh, wl, K, bias, dst, HH, K,
                      blockIdx.y * 128, blockIdx.x * 128);
    } else {
        const int NC = K / 64;
        const int t  = threadIdx.x - 256;                      // 0..127
        const int cid = z * 64 + blockIdx.y * 4 + blockIdx.x;  // 0..255
        const float4* src = ((const float4*)cell_t) + (BH / 4);      // slice 1..
        float4* hc = (float4*)(dout + (size_t)2 * BB * OUTN);        // h_c_1
        const size_t base = (size_t)cid * COPY_F4_CTA;
        for (int c = 0; c < NC; ++c) {
            int jb = (c * COPY_PER_THR) / NC;
            int je = ((c + 1) * COPY_PER_THR) / NC;
            for (int j = jb; j < je; ++j) {
                size_t idx = base + (size_t)j * 128 + t;
                hc[idx] = src[idx];
            }
            __syncthreads();
        }
    }
}

__global__ __launch_bounds__(256, 1)
void out_mma_kernel(const float* __restrict__ bout, float* __restrict__ out) {
    mma_gemm_tile(g_hid_hi, g_hid_lo, HH,
                  g_w_hi + OFF_WOUT, g_w_lo + OFF_WOUT, HH,
                  bout, out, OUTN, HH, blockIdx.y * 128, blockIdx.x * 128);
}

// ---------------------------------------------------------------------------
// conversions: fp32 -> bf16 hi/lo split
// ---------------------------------------------------------------------------
__device__ __forceinline__ void split4(float4 v, __nv_bfloat16* hi, __nv_bfloat16* lo) {
    float f[4] = {v.x, v.y, v.z, v.w};
    union { __nv_bfloat16 h[4]; uint2 u; } H, L;
#pragma unroll
    for (int i = 0; i < 4; i++) {
        __nv_bfloat16 h = __float2bfloat16_rn(f[i]);
        H.h[i] = h;
        L.h[i] = __float2bfloat16_rn(f[i] - __bfloat162float(h));
    }
    *(uint2*)hi = H.u;
    *(uint2*)lo = L.u;
}

__global__ void comb_conv_kernel(const float* __restrict__ sample,
                                 const float* __restrict__ hidden,
                                 const float* __restrict__ d0) {
    int idx = blockIdx.x * blockDim.x + threadIdx.x;   // over BB*KD/4
    if (idx >= BB * KD / 4) return;
    int b  = idx / (KD / 4);
    int c4 = idx % (KD / 4);
    float4 v;
    if (c4 < INN / 4)            v = ((const float4*)sample)[b * (INN/4) + c4];
    else if (c4 < (INN+HH) / 4)  v = ((const float4*)hidden)[b * (HH/4) + (c4 - INN/4)];
    else                         v = ((const float4*)d0)[b * (HH/4) + (c4 - (INN+HH)/4)];
    split4(v, g_comb_hi + idx * 4, g_comb_lo + idx * 4);
}

__global__ void w_conv_kernel(const float* __restrict__ Wi, const float* __restrict__ Wo,
                              const float* __restrict__ Wc, const float* __restrict__ Wf,
                              const float* __restrict__ Wout) {
    int a = blockIdx.y;
    const float* src; size_t off; int n;
    if      (a == 0) { src = Wi;   off = OFF_WI;   n = 512 * 1024; }
    else if (a == 1) { src = Wo;   off = OFF_WO;   n = 512 * 1024; }
    else if (a == 2) { src = Wc;   off = OFF_WC;   n = 512 * 1024; }
    else if (a == 3) { src = Wf;   off = OFF_WF;   n = 512 * 1536; }
    else             { src = Wout; off = OFF_WOUT; n = 512 * 512;  }
    int i = blockIdx.x * blockDim.x + threadIdx.x;
    if (i * 4 >= n) return;
    float4 v = ((const float4*)src)[i];
    split4(v, g_w_hi + off + (size_t)i * 4, g_w_lo + off + (size_t)i * 4);
}

// ---------------------------------------------------------------------------
// fused elementwise (no h_c_1 copy any more) + bf16 split of hidden_new
// ---------------------------------------------------------------------------
__device__ __forceinline__ float sigf(float x) { return 1.0f / (1.0f + expf(-x)); }

__global__ void fused_cell_kernel(const float* __restrict__ cell_t,
                                  float* __restrict__ dout) {
    int idx = blockIdx.x * blockDim.x + threadIdx.x;   // over BH/4
    const int nb4 = BH / 4;
    if (idx >= nb4) return;

    const float4* c4  = (const float4*)cell_t;
    float4* hid = (float4*)(dout + (size_t)BB * OUTN);
    float4* hc  = (float4*)(dout + (size_t)2 * BB * OUTN);
    float4* dv  = (float4*)(dout + (size_t)2 * BB * OUTN + (size_t)KFR * BH);

    float4 zf = ((const float4*)g_z[3])[idx];
    float4 d;
    d.x = 0.5f * sigf(zf.x); d.y = 0.5f * sigf(zf.y);
    d.z = 0.5f * sigf(zf.z); d.w = 0.5f * sigf(zf.w);
    dv[idx] = d;

    float4 w   = make_float4(1.f, 1.f, 1.f, 1.f);
    float4 acc = make_float4(0.f, 0.f, 0.f, 0.f);
    float4 cv  = c4[(size_t)(KFR - 1) * nb4 + idx];
#pragma unroll
    for (int j = KFR - 1; j >= 0; j--) {
        float4 nxt;
        if (j >= 1) nxt = c4[(size_t)(j - 1) * nb4 + idx];   // prefetch next slice
        float fi  = (float)(KFR - 1 - j);
        float inv = 1.0f / (float)(KFR - j);
        w.x *= (fi - d.x) * inv;  w.y *= (fi - d.y) * inv;
        w.z *= (fi - d.z) * inv;  w.w *= (fi - d.w) * inv;
        acc.x = fmaf(w.x, cv.x, acc.x);  acc.y = fmaf(w.y, cv.y, acc.y);
        acc.z = fmaf(w.z, cv.z, acc.z);  acc.w = fmaf(w.w, cv.w, acc.w);
        if (j >= 1) cv = nxt;
    }

    float4 zi = ((const float4*)g_z[0])[idx];
    float4 zo = ((const float4*)g_z[1])[idx];
    float4 zc = ((const float4*)g_z[2])[idx];

    float4 cell;
    cell.x = -acc.x + tanhf(zc.x) * sigf(zi.x);
    cell.y = -acc.y + tanhf(zc.y) * sigf(zi.y);
    cell.z = -acc.z + tanhf(zc.z) * sigf(zi.z);
    cell.w = -acc.w + tanhf(zc.w) * sigf(zi.w);
    hc[(size_t)(KFR - 1) * nb4 + idx] = cell;   // last h_c_1 slice only

    float4 hn;
    hn.x = tanhf(cell.x) * sigf(zo.x);
    hn.y = tanhf(cell.y) * sigf(zo.y);
    hn.z = tanhf(cell.z) * sigf(zo.z);
    hn.w = tanhf(cell.w) * sigf(zo.w);
    hid[idx] = hn;

    split4(hn, g_hid_hi + idx * 4, g_hid_lo + idx * 4);
}

// ---------------------------------------------------------------------------
extern "C" void kernel_launch(void* const* d_in, const int* in_sizes, int n_in,
                              void* d_out_v, int out_size) {
    const float* sample = (const float*)d_in[0];
    const float* hidden = (const float*)d_in[1];
    const float* cell_t = (const float*)d_in[2];
    const float* d0     = (const float*)d_in[3];
    const float* Wc     = (const float*)d_in[4];
    const float* bc     = (const float*)d_in[5];
    const float* Wi     = (const float*)d_in[6];
    const float* bi     = (const float*)d_in[7];
    const float* Wf     = (const float*)d_in[8];
    const float* bf     = (const float*)d_in[9];
    const float* Wo     = (const float*)d_in[10];
    const float* bo     = (const float*)d_in[11];
    const float* Wout   = (const float*)d_in[12];
    const float* bout   = (const float*)d_in[13];
    float* out = (float*)d_out_v;

    cudaFuncSetAttribute(gates_mma_kernel,
                         cudaFuncAttributeMaxDynamicSharedMemorySize, SMEM_TOT);
    cudaFuncSetAttribute(out_mma_kernel,
                         cudaFuncAttributeMaxDynamicSharedMemorySize, SMEM_TOT);

    // 1) build bf16 hi/lo of combined_d and all weights
    comb_conv_kernel<<<(BB * KD / 4 + 255) / 256, 256>>>(sample, hidden, d0);
    dim3 wgrid((512 * 1536 / 4 + 255) / 256, 5);
    w_conv_kernel<<<wgrid, 256>>>(Wi, Wo, Wc, Wf, Wout);

    // 2) 4 gate GEMMs (8 mma warps) + overlapped h_c_1 copy (4 copy warps)
    dim3 ggrid(4, 16, 4);
    gates_mma_kernel<<<ggrid, 384, SMEM_TOT>>>(bi, bo, bc, bf, cell_t, out);

    // 3) fused elementwise (reduced traffic) + hidden_new bf16 split
    fused_cell_kernel<<<(BH / 4 + 255) / 256, 256>>>(cell_t, out);

    // 4) output GEMM
    dim3 ogrid(4, 16, 1);
    out_mma_kernel<<<ogrid, 256, SMEM_TOT>>>(bout, out);
}

// round 7
// speedup vs baseline: 1.1080x; 1.0217x over previous
#include <cuda_runtime.h>
#include <cuda_bf16.h>
#include <math.h>
#include <stdint.h>

#define BB   2048
#define INN  512
#define HH   512
#define KFR  32
#define OUTN 512
#define KD   1536            // IN + 2H (combined_d width)
#define KC   1024            // IN + H
#define BH   (BB*HH)

#define OFF_WI   0
#define OFF_WO   (512*1024)
#define OFF_WC   (2*512*1024)
#define OFF_WF   (3*512*1024)
#define OFF_WOUT (3*512*1024 + 512*1536)
#define W_TOTAL  (OFF_WOUT + 512*512)

#define TILE_B   16384       // one 128x64 bf16 tile in smem
#define STAGE_B  (4*TILE_B)  // Ahi, Alo, Bhi, Blo
#define NSTAGE   3
#define SMEM_TOT (NSTAGE*STAGE_B)   // 196608

// copy duty: h_c_1[0..30] = cell_tensor[1..31], 31*BH floats = 8126464 float4
#define COPY_F4_CTA    31744          // / 256 CTAs
#define COPY_PER_THR   248            // / 128 copy threads

// ---------------- static device scratch ----------------
__device__ __nv_bfloat16 g_comb_hi[BB*KD];
__device__ __nv_bfloat16 g_comb_lo[BB*KD];
__device__ __nv_bfloat16 g_w_hi[W_TOTAL];
__device__ __nv_bfloat16 g_w_lo[W_TOTAL];
__device__ __nv_bfloat16 g_hid_hi[BH];
__device__ __nv_bfloat16 g_hid_lo[BH];
__device__ float g_z[4][BH];          // pre-activations: 0=i, 1=o, 2=c, 3=f

// ---------------- PTX helpers (baseline ISA only) ----------------
__device__ __forceinline__ uint32_t smem_u32(const void* p) {
    return (uint32_t)__cvta_generic_to_shared(p);
}

// named barrier: GEMM warps only (256 threads), leaves copy warps free-running
#define GEMM_BAR() asm volatile("bar.sync 1, 256;" ::: "memory")

__device__ __forceinline__ void cp16(uint32_t daddr, const void* g) {
    asm volatile("cp.async.cg.shared.global [%0], [%1], 16;" :: "r"(daddr), "l"(g) : "memory");
}
#define CP_COMMIT() asm volatile("cp.async.commit_group;" ::: "memory")
template <int N>
__device__ __forceinline__ void cp_wait() {
    asm volatile("cp.async.wait_group %0;" :: "n"(N) : "memory");
}

__device__ __forceinline__ void ldsm4(uint32_t addr, uint32_t* r) {
    asm volatile("ldmatrix.sync.aligned.m8n8.x4.shared.b16 {%0,%1,%2,%3}, [%4];"
        : "=r"(r[0]), "=r"(r[1]), "=r"(r[2]), "=r"(r[3]) : "r"(addr));
}

__device__ __forceinline__ void mma_bf16(float* c, const uint32_t* a, const uint32_t* b) {
    asm volatile("mma.sync.aligned.m16n8k16.row.col.f32.bf16.bf16.f32 "
        "{%0,%1,%2,%3}, {%4,%5,%6,%7}, {%8,%9}, {%0,%1,%2,%3};"
        : "+f"(c[0]), "+f"(c[1]), "+f"(c[2]), "+f"(c[3])
        : "r"(a[0]), "r"(a[1]), "r"(a[2]), "r"(a[3]), "r"(b[0]), "r"(b[1]));
}

// ---------------------------------------------------------------------------
// cp.async loader: one K-chunk (64 cols) of the 4 tiles into one stage.
// 256 GEMM threads; per tile 128 rows x 8 x 16B chunks = 1024 cp16 -> 4/thread
// swizzle: phys_col16 = col16 ^ (row & 7)
// ---------------------------------------------------------------------------
__device__ __forceinline__ void load_stage(uint32_t sbase,
    const char* a_hi, const char* a_lo, const char* b_hi, const char* b_lo,
    int lda_b, int ldb_b, int k0b, int tid) {
    const char* srcs[4] = {a_hi, a_lo, b_hi, b_lo};
    const int lds[4] = {lda_b, lda_b, ldb_b, ldb_b};
#pragma unroll
    for (int t = 0; t < 4; t++) {
#pragma unroll
        for (int i = 0; i < 4; i++) {
            int idx = i * 256 + tid;
            int row = idx >> 3;
            uint32_t ch = (uint32_t)(idx & 7) * 16;
            uint32_t off = (uint32_t)row * 128 + (ch ^ (((uint32_t)row & 7) << 4));
            cp16(sbase + t * TILE_B + off,
                 srcs[t] + (size_t)row * lds[t] + k0b + ch);
        }
    }
}

// ---------------------------------------------------------------------------
// split-bf16 mma.sync GEMM tile (8 warps, 128x128 tile, 3-stage pipeline)
// Uses named barrier 1 (256 threads) so extra warps in the CTA are unaffected.
// ---------------------------------------------------------------------------
__device__ __forceinline__ void mma_gemm_tile(
    const __nv_bfloat16* Ahi, const __nv_bfloat16* Alo, int lda,
    const __nv_bfloat16* Bhi, const __nv_bfloat16* Blo, int ldb,
    const float* __restrict__ bias, float* __restrict__ C, int ldc,
    int K, int blockM, int blockN) {
    extern __shared__ __align__(1024) char dsm[];
    const int tid  = threadIdx.x;
    const int lane = tid & 31;
    const int wid  = tid >> 5;
    const int wm   = wid & 3;    // 0..3 -> 32-row slab
    const int wn   = wid >> 2;   // 0..1 -> 64-col slab
    uint32_t sb = smem_u32(dsm);

    const uint32_t a_kb = ((uint32_t)lane >> 4) * 16;          // 0/16
    const uint32_t b_kb = (((uint32_t)lane >> 3) & 1) * 16;    // 0/16
    uint32_t aRow[2], aXor[2];
#pragma unroll
    for (int mt = 0; mt < 2; mt++) {
        int r = wm * 32 + mt * 16 + (lane & 15);
        aRow[mt] = (uint32_t)r * 128;
        aXor[mt] = ((uint32_t)r & 7) << 4;
    }
    uint32_t bRow[4], bXor[4];
#pragma unroll
    for (int g = 0; g < 4; g++) {
        int r = wn * 64 + g * 16 + (((lane >> 4) << 3) + (lane & 7));
        bRow[g] = (uint32_t)r * 128;
        bXor[g] = ((uint32_t)r & 7) << 4;
    }

    float acc[2][8][4];
#pragma unroll
    for (int mt = 0; mt < 2; mt++)
#pragma unroll
        for (int nt = 0; nt < 8; nt++)
#pragma unroll
            for (int j = 0; j < 4; j++) acc[mt][nt][j] = 0.0f;

    const char* aH = (const char*)(Ahi + (size_t)blockM * lda);
    const char* aL = (const char*)(Alo + (size_t)blockM * lda);
    const char* bH = (const char*)(Bhi + (size_t)blockN * ldb);
    const char* bL = (const char*)(Blo + (size_t)blockN * ldb);
    const int lda_b = lda * 2, ldb_b = ldb * 2;
    const int NC = K / 64;

    load_stage(sb, aH, aL, bH, bL, lda_b, ldb_b, 0, tid);
    CP_COMMIT();
    load_stage(sb + STAGE_B, aH, aL, bH, bL, lda_b, ldb_b, 128, tid);
    CP_COMMIT();

    int stage = 0;
    for (int c = 0; c < NC; ++c) {
        cp_wait<1>();
        GEMM_BAR();
        if (c + 2 < NC) {
            int s2 = stage + 2; if (s2 >= NSTAGE) s2 -= NSTAGE;
            load_stage(sb + (uint32_t)s2 * STAGE_B, aH, aL, bH, bL,
                       lda_b, ldb_b, (c + 2) * 128, tid);
        }
        CP_COMMIT();

        const uint32_t st = sb + (uint32_t)stage * STAGE_B;
#pragma unroll
        for (int kk = 0; kk < 4; kk++) {
            uint32_t ah[2][4], al[2][4];
#pragma unroll
            for (int mt = 0; mt < 2; mt++) {
                uint32_t col = ((uint32_t)(kk * 32) + a_kb) ^ aXor[mt];
                ldsm4(st + 0 * TILE_B + aRow[mt] + col, ah[mt]);
                ldsm4(st + 1 * TILE_B + aRow[mt] + col, al[mt]);
            }
            uint32_t bh[8][2], bl[8][2];
#pragma unroll
            for (int g = 0; g < 4; g++) {
                uint32_t col = ((uint32_t)(kk * 32) + b_kb) ^ bXor[g];
                uint32_t r[4];
                ldsm4(st + 2 * TILE_B + bRow[g] + col, r);
                bh[2*g][0] = r[0]; bh[2*g][1] = r[1];
                bh[2*g+1][0] = r[2]; bh[2*g+1][1] = r[3];
                ldsm4(st + 3 * TILE_B + bRow[g] + col, r);
                bl[2*g][0] = r[0]; bl[2*g][1] = r[1];
                bl[2*g+1][0] = r[2]; bl[2*g+1][1] = r[3];
            }
#pragma unroll
            for (int mt = 0; mt < 2; mt++)
#pragma unroll
                for (int nt = 0; nt < 8; nt++) {
                    mma_bf16(acc[mt][nt], ah[mt], bh[nt]);
                    mma_bf16(acc[mt][nt], ah[mt], bl[nt]);
                    mma_bf16(acc[mt][nt], al[mt], bh[nt]);
                }
        }
        if (++stage >= NSTAGE) stage = 0;
    }

#pragma unroll
    for (int mt = 0; mt < 2; mt++) {
        int r0 = blockM + wm * 32 + mt * 16 + (lane >> 2);
#pragma unroll
        for (int nt = 0; nt < 8; nt++) {
            int col = blockN + wn * 64 + nt * 8 + (lane & 3) * 2;
            float b0 = bias[col], b1 = bias[col + 1];
            float2 v0 = {acc[mt][nt][0] + b0, acc[mt][nt][1] + b1};
            float2 v1 = {acc[mt][nt][2] + b0, acc[mt][nt][3] + b1};
            *(float2*)(C + (size_t)r0 * ldc + col) = v0;
            *(float2*)(C + (size_t)(r0 + 8) * ldc + col) = v1;
        }
    }
}

// ---------------------------------------------------------------------------
// gates GEMM + fully-decoupled h_c_1 shift-copy.
// 384 threads: warps 0-7 GEMM (named bar 1), warps 8-11 free-running copy.
// ---------------------------------------------------------------------------
__global__ __launch_bounds__(384, 1)
void gates_mma_kernel(const float* __restrict__ bi, const float* __restrict__ bo,
                      const float* __restrict__ bc, const float* __restrict__ bf,
                      const float* __restrict__ cell_t, float* __restrict__ dout) {
    int z = blockIdx.z;

    if (threadIdx.x < 256) {
        const __nv_bfloat16 *wh, *wl; const float* bias; int K; float* dst;
        if      (z == 0) { wh = g_w_hi + OFF_WF; wl = g_w_lo + OFF_WF; bias = bf; K = KD; dst = g_z[3]; }
        else if (z == 1) { wh = g_w_hi + OFF_WI; wl = g_w_lo + OFF_WI; bias = bi; K = KC; dst = g_z[0]; }
        else if (z == 2) { wh = g_w_hi + OFF_WO; wl = g_w_lo + OFF_WO; bias = bo; K = KC; dst = g_z[1]; }
        else             { wh = g_w_hi + OFF_WC; wl = g_w_lo + OFF_WC; bias = bc; K = KC; dst = g_z[2]; }
        mma_gemm_tile(g_comb_hi, g_comb_lo, KD, wh, wl, K, bias, dst, HH, K,
                      blockIdx.y * 128, blockIdx.x * 128);
    } else {
        const int t   = threadIdx.x - 256;                     // 0..127
        const int cid = z * 64 + blockIdx.y * 4 + blockIdx.x;  // 0..255
        const float4* src = ((const float4*)cell_t) + (BH / 4);      // slice 1..
        float4* hc = (float4*)(dout + (size_t)2 * BB * OUTN);        // h_c_1
        const size_t base = (size_t)cid * COPY_F4_CTA + t;
#pragma unroll 4
        for (int j = 0; j < COPY_PER_THR; ++j) {
            size_t idx = base + (size_t)j * 128;
            hc[idx] = src[idx];
        }
    }
}

__global__ __launch_bounds__(256, 1)
void out_mma_kernel(const float* __restrict__ bout, float* __restrict__ out) {
    mma_gemm_tile(g_hid_hi, g_hid_lo, HH,
                  g_w_hi + OFF_WOUT, g_w_lo + OFF_WOUT, HH,
                  bout, out, OUTN, HH, blockIdx.y * 128, blockIdx.x * 128);
}

// ---------------------------------------------------------------------------
// conversions: fp32 -> bf16 hi/lo split
// ---------------------------------------------------------------------------
__device__ __forceinline__ void split4(float4 v, __nv_bfloat16* hi, __nv_bfloat16* lo) {
    float f[4] = {v.x, v.y, v.z, v.w};
    union { __nv_bfloat16 h[4]; uint2 u; } H, L;
#pragma unroll
    for (int i = 0; i < 4; i++) {
        __nv_bfloat16 h = __float2bfloat16_rn(f[i]);
        H.h[i] = h;
        L.h[i] = __float2bfloat16_rn(f[i] - __bfloat162float(h));
    }
    *(uint2*)hi = H.u;
    *(uint2*)lo = L.u;
}

__global__ void comb_conv_kernel(const float* __restrict__ sample,
                                 const float* __restrict__ hidden,
                                 const float* __restrict__ d0) {
    int idx = blockIdx.x * blockDim.x + threadIdx.x;   // over BB*KD/4
    if (idx >= BB * KD / 4) return;
    int b  = idx / (KD / 4);
    int c4 = idx % (KD / 4);
    float4 v;
    if (c4 < INN / 4)            v = ((const float4*)sample)[b * (INN/4) + c4];
    else if (c4 < (INN+HH) / 4)  v = ((const float4*)hidden)[b * (HH/4) + (c4 - INN/4)];
    else                         v = ((const float4*)d0)[b * (HH/4) + (c4 - (INN+HH)/4)];
    split4(v, g_comb_hi + idx * 4, g_comb_lo + idx * 4);
}

__global__ void w_conv_kernel(const float* __restrict__ Wi, const float* __restrict__ Wo,
                              const float* __restrict__ Wc, const float* __restrict__ Wf,
                              const float* __restrict__ Wout) {
    int a = blockIdx.y;
    const float* src; size_t off; int n;
    if      (a == 0) { src = Wi;   off = OFF_WI;   n = 512 * 1024; }
    else if (a == 1) { src = Wo;   off = OFF_WO;   n = 512 * 1024; }
    else if (a == 2) { src = Wc;   off = OFF_WC;   n = 512 * 1024; }
    else if (a == 3) { src = Wf;   off = OFF_WF;   n = 512 * 1536; }
    else             { src = Wout; off = OFF_WOUT; n = 512 * 512;  }
    int i = blockIdx.x * blockDim.x + threadIdx.x;
    if (i * 4 >= n) return;
    float4 v = ((const float4*)src)[i];
    split4(v, g_w_hi + off + (size_t)i * 4, g_w_lo + off + (size_t)i * 4);
}

// ---------------------------------------------------------------------------
// fused elementwise, 2 float4 elements per thread for doubled MLP
// ---------------------------------------------------------------------------
__device__ __forceinline__ float sigf(float x) { return 1.0f / (1.0f + expf(-x)); }

__global__ void fused_cell_kernel(const float* __restrict__ cell_t,
                                  float* __restrict__ dout) {
    const int nb4 = BH / 4;
    int i0 = blockIdx.x * (blockDim.x * 2) + threadIdx.x;   // two strided elems
    int i1 = i0 + blockDim.x;

    const float4* c4  = (const float4*)cell_t;
    float4* hid = (float4*)(dout + (size_t)BB * OUTN);
    float4* hc  = (float4*)(dout + (size_t)2 * BB * OUTN);
    float4* dv  = (float4*)(dout + (size_t)2 * BB * OUTN + (size_t)KFR * BH);

    float4 d0v, d1v;
    {
        float4 zf0 = ((const float4*)g_z[3])[i0];
        float4 zf1 = ((const float4*)g_z[3])[i1];
        d0v.x = 0.5f * sigf(zf0.x); d0v.y = 0.5f * sigf(zf0.y);
        d0v.z = 0.5f * sigf(zf0.z); d0v.w = 0.5f * sigf(zf0.w);
        d1v.x = 0.5f * sigf(zf1.x); d1v.y = 0.5f * sigf(zf1.y);
        d1v.z = 0.5f * sigf(zf1.z); d1v.w = 0.5f * sigf(zf1.w);
        dv[i0] = d0v;
        dv[i1] = d1v;
    }

    float4 w0 = make_float4(1.f,1.f,1.f,1.f), w1 = make_float4(1.f,1.f,1.f,1.f);
    float4 a0 = make_float4(0.f,0.f,0.f,0.f), a1 = make_float4(0.f,0.f,0.f,0.f);
    float4 cv0 = c4[(size_t)(KFR - 1) * nb4 + i0];
    float4 cv1 = c4[(size_t)(KFR - 1) * nb4 + i1];
#pragma unroll
    for (int j = KFR - 1; j >= 0; j--) {
        float4 n0, n1;
        if (j >= 1) {
            n0 = c4[(size_t)(j - 1) * nb4 + i0];
            n1 = c4[(size_t)(j - 1) * nb4 + i1];
        }
        float fi  = (float)(KFR - 1 - j);
        float inv = 1.0f / (float)(KFR - j);
        w0.x *= (fi - d0v.x) * inv;  w0.y *= (fi - d0v.y) * inv;
        w0.z *= (fi - d0v.z) * inv;  w0.w *= (fi - d0v.w) * inv;
        w1.x *= (fi - d1v.x) * inv;  w1.y *= (fi - d1v.y) * inv;
        w1.z *= (fi - d1v.z) * inv;  w1.w *= (fi - d1v.w) * inv;
        a0.x = fmaf(w0.x, cv0.x, a0.x);  a0.y = fmaf(w0.y, cv0.y, a0.y);
        a0.z = fmaf(w0.z, cv0.z, a0.z);  a0.w = fmaf(w0.w, cv0.w, a0.w);
        a1.x = fmaf(w1.x, cv1.x, a1.x);  a1.y = fmaf(w1.y, cv1.y, a1.y);
        a1.z = fmaf(w1.z, cv1.z, a1.z);  a1.w = fmaf(w1.w, cv1.w, a1.w);
        if (j >= 1) { cv0 = n0; cv1 = n1; }
    }

#pragma unroll
    for (int e = 0; e < 2; e++) {
        int idx = e ? i1 : i0;
        float4 acc = e ? a1 : a0;
        float4 zi = ((const float4*)g_z[0])[idx];
        float4 zo = ((const float4*)g_z[1])[idx];
        float4 zc = ((const float4*)g_z[2])[idx];

        float4 cell;
        cell.x = -acc.x + tanhf(zc.x) * sigf(zi.x);
        cell.y = -acc.y + tanhf(zc.y) * sigf(zi.y);
        cell.z = -acc.z + tanhf(zc.z) * sigf(zi.z);
        cell.w = -acc.w + tanhf(zc.w) * sigf(zi.w);
        hc[(size_t)(KFR - 1) * nb4 + idx] = cell;

        float4 hn;
        hn.x = tanhf(cell.x) * sigf(zo.x);
        hn.y = tanhf(cell.y) * sigf(zo.y);
        hn.z = tanhf(cell.z) * sigf(zo.z);
        hn.w = tanhf(cell.w) * sigf(zo.w);
        hid[idx] = hn;

        split4(hn, g_hid_hi + (size_t)idx * 4, g_hid_lo + (size_t)idx * 4);
    }
}

// ---------------------------------------------------------------------------
extern "C" void kernel_launch(void* const* d_in, const int* in_sizes, int n_in,
                              void* d_out_v, int out_size) {
    const float* sample = (const float*)d_in[0];
    const float* hidden = (const float*)d_in[1];
    const float* cell_t = (const float*)d_in[2];
    const float* d0     = (const float*)d_in[3];
    const float* Wc     = (const float*)d_in[4];
    const float* bc     = (const float*)d_in[5];
    const float* Wi     = (const float*)d_in[6];
    const float* bi     = (const float*)d_in[7];
    const float* Wf     = (const float*)d_in[8];
    const float* bf     = (const float*)d_in[9];
    const float* Wo     = (const float*)d_in[10];
    const float* bo     = (const float*)d_in[11];
    const float* Wout   = (const float*)d_in[12];
    const float* bout   = (const float*)d_in[13];
    float* out = (float*)d_out_v;

    cudaFuncSetAttribute(gates_mma_kernel,
                         cudaFuncAttributeMaxDynamicSharedMemorySize, SMEM_TOT);
    cudaFuncSetAttribute(out_mma_kernel,
                         cudaFuncAttributeMaxDynamicSharedMemorySize, SMEM_TOT);

    // 1) build bf16 hi/lo of combined_d and all weights
    comb_conv_kernel<<<(BB * KD / 4 + 255) / 256, 256>>>(sample, hidden, d0);
    dim3 wgrid((512 * 1536 / 4 + 255) / 256, 5);
    w_conv_kernel<<<wgrid, 256>>>(Wi, Wo, Wc, Wf, Wout);

    // 2) 4 gate GEMMs (8 mma warps, bar 1) + free-running h_c_1 copy (4 warps)
    dim3 ggrid(4, 16, 4);
    gates_mma_kernel<<<ggrid, 384, SMEM_TOT>>>(bi, bo, bc, bf, cell_t, out);

    // 3) fused elementwise (2 elems/thread) + hidden_new bf16 split
    fused_cell_kernel<<<BH / 4 / 512, 256>>>(cell_t, out);

    // 4) output GEMM
    dim3 ogrid(4, 16, 1);
    out_mma_kernel<<<ogrid, 256, SMEM_TOT>>>(bout, out);
}

// round 8
// speedup vs baseline: 1.1259x; 1.0162x over previous
#include <cuda_runtime.h>
#include <cuda_bf16.h>
#include <math.h>
#include <stdint.h>

#define BB   2048
#define INN  512
#define HH   512
#define KFR  32
#define OUTN 512
#define KD   1536            // IN + 2H (combined_d width)
#define KC   1024            // IN + H
#define BH   (BB*HH)

#define OFF_WI   0
#define OFF_WO   (512*1024)
#define OFF_WC   (2*512*1024)
#define OFF_WF   (3*512*1024)
#define OFF_WOUT (3*512*1024 + 512*1536)
#define W_TOTAL  (OFF_WOUT + 512*512)

// K-chunk 32: one 128x32 bf16 tile = 8KB; stage = 4 tiles = 32KB; 3 stages = 96KB
#define TILE_B   8192
#define STAGE_B  (4*TILE_B)
#define NSTAGE   3
#define SMEM_TOT (NSTAGE*STAGE_B)   // 98304 -> 2 CTAs/SM

// ---------------- static device scratch ----------------
__device__ __nv_bfloat16 g_comb_hi[BB*KD];
__device__ __nv_bfloat16 g_comb_lo[BB*KD];
__device__ __nv_bfloat16 g_w_hi[W_TOTAL];
__device__ __nv_bfloat16 g_w_lo[W_TOTAL];
__device__ __nv_bfloat16 g_hid_hi[BH];
__device__ __nv_bfloat16 g_hid_lo[BH];
__device__ float g_z[4][BH];          // pre-activations: 0=i, 1=o, 2=c, 3=f

// ---------------- PTX helpers (baseline ISA only) ----------------
__device__ __forceinline__ uint32_t smem_u32(const void* p) {
    return (uint32_t)__cvta_generic_to_shared(p);
}

__device__ __forceinline__ void cp16(uint32_t daddr, const void* g) {
    asm volatile("cp.async.cg.shared.global [%0], [%1], 16;" :: "r"(daddr), "l"(g) : "memory");
}
#define CP_COMMIT() asm volatile("cp.async.commit_group;" ::: "memory")
template <int N>
__device__ __forceinline__ void cp_wait() {
    asm volatile("cp.async.wait_group %0;" :: "n"(N) : "memory");
}

__device__ __forceinline__ void ldsm4(uint32_t addr, uint32_t* r) {
    asm volatile("ldmatrix.sync.aligned.m8n8.x4.shared.b16 {%0,%1,%2,%3}, [%4];"
        : "=r"(r[0]), "=r"(r[1]), "=r"(r[2]), "=r"(r[3]) : "r"(addr));
}

__device__ __forceinline__ void mma_bf16(float* c, const uint32_t* a, const uint32_t* b) {
    asm volatile("mma.sync.aligned.m16n8k16.row.col.f32.bf16.bf16.f32 "
        "{%0,%1,%2,%3}, {%4,%5,%6,%7}, {%8,%9}, {%0,%1,%2,%3};"
        : "+f"(c[0]), "+f"(c[1]), "+f"(c[2]), "+f"(c[3])
        : "r"(a[0]), "r"(a[1]), "r"(a[2]), "r"(a[3]), "r"(b[0]), "r"(b[1]));
}

// ---------------------------------------------------------------------------
// cp.async loader: one K-chunk (32 cols = 64B rows) of 4 tiles into one stage.
// Per tile: 128 rows x 4 x 16B = 512 cp16; 4 tiles = 2048 -> 8 per thread.
// SW64 swizzle: phys = row*64 + (col16 ^ (((row>>1)&3)<<4))
// ---------------------------------------------------------------------------
__device__ __forceinline__ void load_stage(uint32_t sbase,
    const char* a_hi, const char* a_lo, const char* b_hi, const char* b_lo,
    int lda_b, int ldb_b, int k0b, int tid) {
    const char* srcs[4] = {a_hi, a_lo, b_hi, b_lo};
    const int lds[4] = {lda_b, lda_b, ldb_b, ldb_b};
#pragma unroll
    for (int t = 0; t < 4; t++) {
#pragma unroll
        for (int i = 0; i < 2; i++) {
            int idx = i * 256 + tid;
            int row = idx >> 2;
            uint32_t ch = (uint32_t)(idx & 3) * 16;
            uint32_t off = (uint32_t)row * 64 + (ch ^ ((((uint32_t)row >> 1) & 3) << 4));
            cp16(sbase + t * TILE_B + off,
                 srcs[t] + (size_t)row * lds[t] + k0b + ch);
        }
    }
}

// ---------------------------------------------------------------------------
// split-bf16 mma.sync GEMM tile: 128x128 tile, 8 warps (4Mx2N), warp 32x64,
// K-chunk 32, 3-stage pipeline, 2 CTAs/SM.
// ---------------------------------------------------------------------------
__device__ __forceinline__ void mma_gemm_tile(
    const __nv_bfloat16* Ahi, const __nv_bfloat16* Alo, int lda,
    const __nv_bfloat16* Bhi, const __nv_bfloat16* Blo, int ldb,
    const float* __restrict__ bias, float* __restrict__ C, int ldc,
    int K, int blockM, int blockN) {
    extern __shared__ __align__(1024) char dsm[];
    const int tid  = threadIdx.x;
    const int lane = tid & 31;
    const int wid  = tid >> 5;
    const int wm   = wid & 3;    // 0..3 -> 32-row slab
    const int wn   = wid >> 2;   // 0..1 -> 64-col slab
    uint32_t sb = smem_u32(dsm);

    const uint32_t a_kb = ((uint32_t)lane >> 4) * 16;          // 0/16
    const uint32_t b_kb = (((uint32_t)lane >> 3) & 1) * 16;    // 0/16
    uint32_t aRow[2], aXor[2];
#pragma unroll
    for (int mt = 0; mt < 2; mt++) {
        int r = wm * 32 + mt * 16 + (lane & 15);
        aRow[mt] = (uint32_t)r * 64;
        aXor[mt] = (((uint32_t)r >> 1) & 3) << 4;
    }
    uint32_t bRow[4], bXor[4];
#pragma unroll
    for (int g = 0; g < 4; g++) {
        int r = wn * 64 + g * 16 + (((lane >> 4) << 3) + (lane & 7));
        bRow[g] = (uint32_t)r * 64;
        bXor[g] = (((uint32_t)r >> 1) & 3) << 4;
    }

    float acc[2][8][4];
#pragma unroll
    for (int mt = 0; mt < 2; mt++)
#pragma unroll
        for (int nt = 0; nt < 8; nt++)
#pragma unroll
            for (int j = 0; j < 4; j++) acc[mt][nt][j] = 0.0f;

    const char* aH = (const char*)(Ahi + (size_t)blockM * lda);
    const char* aL = (const char*)(Alo + (size_t)blockM * lda);
    const char* bH = (const char*)(Bhi + (size_t)blockN * ldb);
    const char* bL = (const char*)(Blo + (size_t)blockN * ldb);
    const int lda_b = lda * 2, ldb_b = ldb * 2;
    const int NC = K / 32;

    load_stage(sb, aH, aL, bH, bL, lda_b, ldb_b, 0, tid);
    CP_COMMIT();
    load_stage(sb + STAGE_B, aH, aL, bH, bL, lda_b, ldb_b, 64, tid);
    CP_COMMIT();

    int stage = 0;
    for (int c = 0; c < NC; ++c) {
        cp_wait<1>();
        __syncthreads();
        if (c + 2 < NC) {
            int s2 = stage + 2; if (s2 >= NSTAGE) s2 -= NSTAGE;
            load_stage(sb + (uint32_t)s2 * STAGE_B, aH, aL, bH, bL,
                       lda_b, ldb_b, (c + 2) * 64, tid);
        }
        CP_COMMIT();

        const uint32_t st = sb + (uint32_t)stage * STAGE_B;
#pragma unroll
        for (int kk = 0; kk < 2; kk++) {
            uint32_t ah[2][4], al[2][4];
#pragma unroll
            for (int mt = 0; mt < 2; mt++) {
                uint32_t col = (uint32_t)(kk * 32) + a_kb;
                ldsm4(st + 0 * TILE_B + aRow[mt] + (col ^ aXor[mt]), ah[mt]);
                ldsm4(st + 1 * TILE_B + aRow[mt] + (col ^ aXor[mt]), al[mt]);
            }
#pragma unroll
            for (int g = 0; g < 4; g++) {
                uint32_t col = (uint32_t)(kk * 32) + b_kb;
                uint32_t bh[4], bl[4];
                ldsm4(st + 2 * TILE_B + bRow[g] + (col ^ bXor[g]), bh);
                ldsm4(st + 3 * TILE_B + bRow[g] + (col ^ bXor[g]), bl);
#pragma unroll
                for (int mt = 0; mt < 2; mt++) {
                    mma_bf16(acc[mt][2*g],   ah[mt], bh);
                    mma_bf16(acc[mt][2*g],   ah[mt], bl);
                    mma_bf16(acc[mt][2*g],   al[mt], bh);
                    mma_bf16(acc[mt][2*g+1], ah[mt], bh + 2);
                    mma_bf16(acc[mt][2*g+1], ah[mt], bl + 2);
                    mma_bf16(acc[mt][2*g+1], al[mt], bh + 2);
                }
            }
        }
        if (++stage >= NSTAGE) stage = 0;
    }

    // epilogue: add bias, store fp32
#pragma unroll
    for (int mt = 0; mt < 2; mt++) {
        int r0 = blockM + wm * 32 + mt * 16 + (lane >> 2);
#pragma unroll
        for (int nt = 0; nt < 8; nt++) {
            int col = blockN + wn * 64 + nt * 8 + (lane & 3) * 2;
            float b0 = bias[col], b1 = bias[col + 1];
            float2 v0 = {acc[mt][nt][0] + b0, acc[mt][nt][1] + b1};
            float2 v1 = {acc[mt][nt][2] + b0, acc[mt][nt][3] + b1};
            *(float2*)(C + (size_t)r0 * ldc + col) = v0;
            *(float2*)(C + (size_t)(r0 + 8) * ldc + col) = v1;
        }
    }
}

// ---------------------------------------------------------------------------
// z order: 0 = Wf (K=1536, longest -> first), then i, o, c
__global__ __launch_bounds__(256, 2)
void gates_mma_kernel(const float* __restrict__ bi, const float* __restrict__ bo,
                      const float* __restrict__ bc, const float* __restrict__ bf) {
    int z = blockIdx.z;
    const __nv_bfloat16 *wh, *wl; const float* bias; int K; float* dst;
    if      (z == 0) { wh = g_w_hi + OFF_WF; wl = g_w_lo + OFF_WF; bias = bf; K = KD; dst = g_z[3]; }
    else if (z == 1) { wh = g_w_hi + OFF_WI; wl = g_w_lo + OFF_WI; bias = bi; K = KC; dst = g_z[0]; }
    else if (z == 2) { wh = g_w_hi + OFF_WO; wl = g_w_lo + OFF_WO; bias = bo; K = KC; dst = g_z[1]; }
    else             { wh = g_w_hi + OFF_WC; wl = g_w_lo + OFF_WC; bias = bc; K = KC; dst = g_z[2]; }
    mma_gemm_tile(g_comb_hi, g_comb_lo, KD, wh, wl, K, bias, dst, HH, K,
                  blockIdx.y * 128, blockIdx.x * 128);
}

__global__ __launch_bounds__(256, 2)
void out_mma_kernel(const float* __restrict__ bout, float* __restrict__ out) {
    mma_gemm_tile(g_hid_hi, g_hid_lo, HH,
                  g_w_hi + OFF_WOUT, g_w_lo + OFF_WOUT, HH,
                  bout, out, OUTN, HH, blockIdx.y * 128, blockIdx.x * 128);
}

// ---------------------------------------------------------------------------
// conversions: fp32 -> bf16 hi/lo split
// ---------------------------------------------------------------------------
__device__ __forceinline__ void split4(float4 v, __nv_bfloat16* hi, __nv_bfloat16* lo) {
    float f[4] = {v.x, v.y, v.z, v.w};
    union { __nv_bfloat16 h[4]; uint2 u; } H, L;
#pragma unroll
    for (int i = 0; i < 4; i++) {
        __nv_bfloat16 h = __float2bfloat16_rn(f[i]);
        H.h[i] = h;
        L.h[i] = __float2bfloat16_rn(f[i] - __bfloat162float(h));
    }
    *(uint2*)hi = H.u;
    *(uint2*)lo = L.u;
}

__global__ void comb_conv_kernel(const float* __restrict__ sample,
                                 const float* __restrict__ hidden,
                                 const float* __restrict__ d0) {
    int idx = blockIdx.x * blockDim.x + threadIdx.x;   // over BB*KD/4
    if (idx >= BB * KD / 4) return;
    int b  = idx / (KD / 4);
    int c4 = idx % (KD / 4);
    float4 v;
    if (c4 < INN / 4)            v = ((const float4*)sample)[b * (INN/4) + c4];
    else if (c4 < (INN+HH) / 4)  v = ((const float4*)hidden)[b * (HH/4) + (c4 - INN/4)];
    else                         v = ((const float4*)d0)[b * (HH/4) + (c4 - (INN+HH)/4)];
    split4(v, g_comb_hi + idx * 4, g_comb_lo + idx * 4);
}

__global__ void w_conv_kernel(const float* __restrict__ Wi, const float* __restrict__ Wo,
                              const float* __restrict__ Wc, const float* __restrict__ Wf,
                              const float* __restrict__ Wout) {
    int a = blockIdx.y;
    const float* src; size_t off; int n;
    if      (a == 0) { src = Wi;   off = OFF_WI;   n = 512 * 1024; }
    else if (a == 1) { src = Wo;   off = OFF_WO;   n = 512 * 1024; }
    else if (a == 2) { src = Wc;   off = OFF_WC;   n = 512 * 1024; }
    else if (a == 3) { src = Wf;   off = OFF_WF;   n = 512 * 1536; }
    else             { src = Wout; off = OFF_WOUT; n = 512 * 512;  }
    int i = blockIdx.x * blockDim.x + threadIdx.x;
    if (i * 4 >= n) return;
    float4 v = ((const float4*)src)[i];
    split4(v, g_w_hi + off + (size_t)i * 4, g_w_lo + off + (size_t)i * 4);
}

// ---------------------------------------------------------------------------
// fused elementwise (R4 form: includes h_c_1 shift-copy) + bf16 split
// ---------------------------------------------------------------------------
__device__ __forceinline__ float sigf(float x) { return 1.0f / (1.0f + expf(-x)); }

__global__ void fused_cell_kernel(const float* __restrict__ cell_t,
                                  float* __restrict__ dout) {
    int idx = blockIdx.x * blockDim.x + threadIdx.x;   // over BH/4
    const int nb4 = BH / 4;
    if (idx >= nb4) return;

    const float4* c4  = (const float4*)cell_t;
    float4* hid = (float4*)(dout + (size_t)BB * OUTN);
    float4* hc  = (float4*)(dout + (size_t)2 * BB * OUTN);
    float4* dv  = (float4*)(dout + (size_t)2 * BB * OUTN + (size_t)KFR * BH);

    float4 zf = ((const float4*)g_z[3])[idx];
    float4 d;
    d.x = 0.5f * sigf(zf.x); d.y = 0.5f * sigf(zf.y);
    d.z = 0.5f * sigf(zf.z); d.w = 0.5f * sigf(zf.w);
    dv[idx] = d;

    float4 w   = make_float4(1.f, 1.f, 1.f, 1.f);
    float4 acc = make_float4(0.f, 0.f, 0.f, 0.f);
    float4 cv  = c4[(size_t)(KFR - 1) * nb4 + idx];
#pragma unroll
    for (int j = KFR - 1; j >= 0; j--) {
        float4 nxt;
        if (j >= 1) nxt = c4[(size_t)(j - 1) * nb4 + idx];   // prefetch next slice
        float fi  = (float)(KFR - 1 - j);
        float inv = 1.0f / (float)(KFR - j);
        w.x *= (fi - d.x) * inv;  w.y *= (fi - d.y) * inv;
        w.z *= (fi - d.z) * inv;  w.w *= (fi - d.w) * inv;
        acc.x = fmaf(w.x, cv.x, acc.x);  acc.y = fmaf(w.y, cv.y, acc.y);
        acc.z = fmaf(w.z, cv.z, acc.z);  acc.w = fmaf(w.w, cv.w, acc.w);
        if (j >= 1) { hc[(size_t)(j - 1) * nb4 + idx] = cv; cv = nxt; }
    }

    float4 zi = ((const float4*)g_z[0])[idx];
    float4 zo = ((const float4*)g_z[1])[idx];
    float4 zc = ((const float4*)g_z[2])[idx];

    float4 cell;
    cell.x = -acc.x + tanhf(zc.x) * sigf(zi.x);
    cell.y = -acc.y + tanhf(zc.y) * sigf(zi.y);
    cell.z = -acc.z + tanhf(zc.z) * sigf(zi.z);
    cell.w = -acc.w + tanhf(zc.w) * sigf(zi.w);
    hc[(size_t)(KFR - 1) * nb4 + idx] = cell;

    float4 hn;
    hn.x = tanhf(cell.x) * sigf(zo.x);
    hn.y = tanhf(cell.y) * sigf(zo.y);
    hn.z = tanhf(cell.z) * sigf(zo.z);
    hn.w = tanhf(cell.w) * sigf(zo.w);
    hid[idx] = hn;

    split4(hn, g_hid_hi + idx * 4, g_hid_lo + idx * 4);
}

// ---------------------------------------------------------------------------
extern "C" void kernel_launch(void* const* d_in, const int* in_sizes, int n_in,
                              void* d_out_v, int out_size) {
    const float* sample = (const float*)d_in[0];
    const float* hidden = (const float*)d_in[1];
    const float* cell_t = (const float*)d_in[2];
    const float* d0     = (const float*)d_in[3];
    const float* Wc     = (const float*)d_in[4];
    const float* bc     = (const float*)d_in[5];
    const float* Wi     = (const float*)d_in[6];
    const float* bi     = (const float*)d_in[7];
    const float* Wf     = (const float*)d_in[8];
    const float* bf     = (const float*)d_in[9];
    const float* Wo     = (const float*)d_in[10];
    const float* bo     = (const float*)d_in[11];
    const float* Wout   = (const float*)d_in[12];
    const float* bout   = (const float*)d_in[13];
    float* out = (float*)d_out_v;

    cudaFuncSetAttribute(gates_mma_kernel,
                         cudaFuncAttributeMaxDynamicSharedMemorySize, SMEM_TOT);
    cudaFuncSetAttribute(out_mma_kernel,
                         cudaFuncAttributeMaxDynamicSharedMemorySize, SMEM_TOT);

    // 1) build bf16 hi/lo of combined_d and all weights
    comb_conv_kernel<<<(BB * KD / 4 + 255) / 256, 256>>>(sample, hidden, d0);
    dim3 wgrid((512 * 1536 / 4 + 255) / 256, 5);
    w_conv_kernel<<<wgrid, 256>>>(Wi, Wo, Wc, Wf, Wout);

    // 2) 4 gate GEMMs, 128x128 tiles, 2 CTAs/SM -> single wave (256 CTAs)
    dim3 ggrid(4, 16, 4);
    gates_mma_kernel<<<ggrid, 256, SMEM_TOT>>>(bi, bo, bc, bf);

    // 3) fused elementwise (incl. h_c_1 copy) + hidden_new bf16 split
    fused_cell_kernel<<<(BH / 4 + 255) / 256, 256>>>(cell_t, out);

    // 4) output GEMM
    dim3 ogrid(4, 16, 1);
    out_mma_kernel<<<ogrid, 256, SMEM_TOT>>>(bout, out);
}